// round 16
// baseline (speedup 1.0000x reference)
#include <cuda_runtime.h>
#include <cuda_bf16.h>
#include <math.h>
#include <stdint.h>

// Problem constants (fixed by the reference)
#define B_  2
#define T_  2048
#define C_  1024
#define NH_ 16
#define NKV_ 4
#define HD_ 64
#define VEC_ 32
#define M_  (B_ * T_)      // 4096 token rows
#define NQKV_ 1536         // fused q(1024) | k(256) | v(256) columns

// tcgen05 is arch-conditional: only in the sm_103a/sm_100a passes. The
// baseline compute_103 target gets SIMT fallback bodies.
#if defined(__CUDA_ARCH_FEAT_SM103_ALL) || defined(__CUDA_ARCH_FEAT_SM100_ALL) || \
    defined(__CUDA_ARCH_FEAT_SM101_ALL)
#define TC_OK 1
#else
#define TC_OK 0
#endif

// ---------------------------------------------------------------------------
// Scratch (static device globals; no runtime allocation allowed)
// ---------------------------------------------------------------------------
__device__ __align__(16) __nv_bfloat16 g_xs_hi[M_ * C_];       // x split
__device__ __align__(16) __nv_bfloat16 g_xs_lo[M_ * C_];
__device__ __align__(16) __nv_bfloat16 g_ys_hi[M_ * C_];       // attn out split
__device__ __align__(16) __nv_bfloat16 g_ys_lo[M_ * C_];
__device__ __align__(16) __nv_bfloat16 g_wqkv_hi[NQKV_ * C_];  // [N,K] transposed
__device__ __align__(16) __nv_bfloat16 g_wqkv_lo[NQKV_ * C_];
__device__ __align__(16) __nv_bfloat16 g_wproj_hi[C_ * C_];    // [N,K] transposed
__device__ __align__(16) __nv_bfloat16 g_wproj_lo[C_ * C_];
__device__ float g_gate[M_ * NKV_];        // 2*sigmoid(x[:,:32] @ Wgate)
// attention operands, bf16 hi/lo split
__device__ __align__(16) __nv_bfloat16 g_qs_hi[M_ * NH_ * HD_];   // [B,NH,T,HD]
__device__ __align__(16) __nv_bfloat16 g_qs_lo[M_ * NH_ * HD_];
__device__ __align__(16) __nv_bfloat16 g_ks_hi[M_ * NKV_ * HD_];  // [B,NKV,T,HD]
__device__ __align__(16) __nv_bfloat16 g_ks_lo[M_ * NKV_ * HD_];
__device__ __align__(16) __nv_bfloat16 g_vn_hi[M_ * NKV_ * HD_];  // [B,NKV,T,HD]
__device__ __align__(16) __nv_bfloat16 g_vn_lo[M_ * NKV_ * HD_];
__device__ __align__(16) __nv_bfloat16 g_vts_hi[M_ * NKV_ * HD_]; // [B,NKV,HD,T]
__device__ __align__(16) __nv_bfloat16 g_vts_lo[M_ * NKV_ * HD_];

// ---------------------------------------------------------------------------
// PTX helpers
// ---------------------------------------------------------------------------
__device__ __forceinline__ uint32_t smem_u32(const void* p) {
    uint32_t a;
    asm("{ .reg .u64 t; cvta.to.shared.u64 t, %1; cvt.u32.u64 %0, t; }"
        : "=r"(a) : "l"(p));
    return a;
}
__device__ __forceinline__ uint32_t elect_one() {
    uint32_t pred;
    asm volatile("{\n\t.reg .pred p;\n\telect.sync _|p, 0xFFFFFFFF;\n\t"
                 "selp.b32 %0, 1, 0, p;\n\t}" : "=r"(pred));
    return pred;
}
#define TC_ALLOC(sm, n)   asm volatile("tcgen05.alloc.cta_group::1.sync.aligned.shared::cta.b32 [%0], %1;" :: "r"(sm), "r"((uint32_t)(n)) : "memory")
#define TC_DEALLOC(t, n)  asm volatile("tcgen05.dealloc.cta_group::1.sync.aligned.b32 %0, %1;" :: "r"(t), "r"((uint32_t)(n)))
#define TC_RELINQ()       asm volatile("tcgen05.relinquish_alloc_permit.cta_group::1.sync.aligned;")
#define TC_COMMIT(mbar)   asm volatile("tcgen05.commit.cta_group::1.mbarrier::arrive::one.shared::cluster.b64 [%0];" :: "r"(mbar) : "memory")
#define TC_FENCE_AFTER()  asm volatile("tcgen05.fence::after_thread_sync;" ::: "memory")
#define TC_FENCE_BEFORE() asm volatile("tcgen05.fence::before_thread_sync;" ::: "memory")
#define TC_WAIT_LD()      asm volatile("tcgen05.wait::ld.sync.aligned;" ::: "memory")
#define TC_WAIT_ST()      asm volatile("tcgen05.wait::st.sync.aligned;" ::: "memory")
#define MBAR_INIT(sm, n)  asm volatile("mbarrier.init.shared.b64 [%0], %1;" :: "r"(sm), "r"((uint32_t)(n)) : "memory")
#define FENCE_ASYNC()     asm volatile("fence.proxy.async.shared::cta;" ::: "memory")
#define CP_ASYNC16(dst, src) asm volatile("cp.async.cg.shared.global [%0], [%1], 16;" :: "r"(dst), "l"(src) : "memory")
#define CP_COMMIT()       asm volatile("cp.async.commit_group;" ::: "memory")
#define CP_WAIT0()        asm volatile("cp.async.wait_group 0;" ::: "memory")
#define CP_WAIT1()        asm volatile("cp.async.wait_group 1;" ::: "memory")

__device__ __forceinline__ void mbar_wait(uint32_t mbar, uint32_t parity) {
    asm volatile(
        "{\n\t.reg .pred P;\n\t"
        "W%=:\n\t"
        "mbarrier.try_wait.parity.acquire.cta.shared::cta.b64 P, [%0], %1, 0x989680;\n\t"
        "@P bra D%=;\n\t"
        "bra W%=;\n\t"
        "D%=:\n\t}"
        :: "r"(mbar), "r"(parity) : "memory");
}
__device__ __forceinline__ float ex2_approx(float x) {
    float r;
    asm("ex2.approx.ftz.f32 %0, %1;" : "=f"(r) : "f"(x));
    return r;
}

#if TC_OK
// SS-mode bf16 MMA, cta_group::1, fp32 accum
__device__ __forceinline__ void mma_f16_ss(uint32_t d, uint64_t a, uint64_t b,
                                           uint32_t idesc, uint32_t en) {
    asm volatile(
        "{\n\t.reg .pred p;\n\t"
        "setp.ne.u32 p, %4, 0;\n\t"
        "tcgen05.mma.cta_group::1.kind::f16 [%0], %1, %2, %3, {%5, %5, %5, %5}, p;\n\t"
        "}"
        :: "r"(d), "l"(a), "l"(b), "r"(idesc), "r"(en), "r"(0u)
        : "memory");
}
// TS-mode bf16 MMA: A in TMEM, B in SMEM
__device__ __forceinline__ void mma_f16_ts(uint32_t d, uint32_t a, uint64_t b,
                                           uint32_t idesc, uint32_t en) {
    asm volatile(
        "{\n\t.reg .pred p;\n\t"
        "setp.ne.u32 p, %4, 0;\n\t"
        "tcgen05.mma.cta_group::1.kind::f16 [%0], [%1], %2, %3, {%5, %5, %5, %5}, p;\n\t"
        "}"
        :: "r"(d), "r"(a), "l"(b), "r"(idesc), "r"(en), "r"(0u)
        : "memory");
}

#define LDTM_X32(r, addr) \
    asm volatile( \
        "tcgen05.ld.sync.aligned.32x32b.x32.b32 " \
        "{%0, %1, %2, %3, %4, %5, %6, %7, " \
        " %8, %9, %10, %11, %12, %13, %14, %15, " \
        " %16, %17, %18, %19, %20, %21, %22, %23, " \
        " %24, %25, %26, %27, %28, %29, %30, %31}, [%32];" \
        : "=r"((r)[0]),  "=r"((r)[1]),  "=r"((r)[2]),  "=r"((r)[3]), \
          "=r"((r)[4]),  "=r"((r)[5]),  "=r"((r)[6]),  "=r"((r)[7]), \
          "=r"((r)[8]),  "=r"((r)[9]),  "=r"((r)[10]), "=r"((r)[11]), \
          "=r"((r)[12]), "=r"((r)[13]), "=r"((r)[14]), "=r"((r)[15]), \
          "=r"((r)[16]), "=r"((r)[17]), "=r"((r)[18]), "=r"((r)[19]), \
          "=r"((r)[20]), "=r"((r)[21]), "=r"((r)[22]), "=r"((r)[23]), \
          "=r"((r)[24]), "=r"((r)[25]), "=r"((r)[26]), "=r"((r)[27]), \
          "=r"((r)[28]), "=r"((r)[29]), "=r"((r)[30]), "=r"((r)[31]) \
        : "r"(addr))

#define STTM_X16(addr, r) \
    asm volatile( \
        "tcgen05.st.sync.aligned.32x32b.x16.b32 [%0], " \
        "{%1, %2, %3, %4, %5, %6, %7, %8, " \
        " %9, %10, %11, %12, %13, %14, %15, %16};" \
        :: "r"(addr), \
           "r"((r)[0]),  "r"((r)[1]),  "r"((r)[2]),  "r"((r)[3]), \
           "r"((r)[4]),  "r"((r)[5]),  "r"((r)[6]),  "r"((r)[7]), \
           "r"((r)[8]),  "r"((r)[9]),  "r"((r)[10]), "r"((r)[11]), \
           "r"((r)[12]), "r"((r)[13]), "r"((r)[14]), "r"((r)[15]) \
        : "memory")
#endif  // TC_OK

// 64-bit SMEM descriptor: SW128, version=1 (Blackwell), LBO=1, SBO=64
static __device__ __forceinline__ uint64_t smem_desc_sw128(uint32_t addr) {
    const uint64_t base =
        (uint64_t(2)  << 61) | (uint64_t(1) << 46) |
        (uint64_t(64) << 32) | (uint64_t(1) << 16);
    return base | ((uint64_t)(addr >> 4) & 0x3FFF);
}
#define SW128(off) ((off) ^ (((off) >> 3) & 0x70))

// idesc: dtype=F32, atype=BF16, btype=BF16 (K-major both)
#define GEMM_IDESC ((1u << 4) | (1u << 7) | (1u << 10) | ((128u / 8) << 17) | ((128u / 16) << 24))
#define ATT_IDESC  ((1u << 4) | (1u << 7) | (1u << 10) | ((64u / 8) << 17) | ((128u / 16) << 24))

__device__ __forceinline__ uint32_t b2u(__nv_bfloat162 v) {
    return *(uint32_t*)&v;
}

// ---------------------------------------------------------------------------
// Fused QKV post-processing for one (token row, 64-col head), shared by the
// tcgen05 epilogue and the SIMT fallback. v[64] = fp32 GEMM accum for this
// (row, head). gcol = global output column base (multiple of 64).
//   gcol <  1024: q head  -> RoPE + RMSNorm -> qs hi/lo
//   gcol <  1280: k head  -> RoPE + RMSNorm -> ks hi/lo
//   else        : v head  -> + gate*ve      -> vn hi/lo (untransposed)
// ---------------------------------------------------------------------------
__device__ __forceinline__ void fused_rowhead(
    const float* __restrict__ v, int row, int gcol,
    const float* __restrict__ cosb, const float* __restrict__ sinb,
    const float* __restrict__ ve, const float* __restrict__ gate) {
    const int b = row / T_;
    const int t = row % T_;
    if (gcol < 1280) {
        float o1[32], o2[32];
        float sq = 0.f;
#pragma unroll
        for (int i = 0; i < 32; i++) {
            float c = cosb[t * 32 + i];
            float s = sinb[t * 32 + i];
            float x1 = v[i], x2 = v[32 + i];
            o1[i] = x1 * c + x2 * s;
            o2[i] = -x1 * s + x2 * c;
            sq += o1[i] * o1[i] + o2[i] * o2[i];
        }
        float sc = rsqrtf(sq * (1.0f / HD_) + 1.1920929e-7f);
        __nv_bfloat16 *dhi, *dlo;
        if (gcol < 1024) {
            int h = gcol >> 6;
            size_t base = ((size_t)(b * NH_ + h) * T_ + t) * HD_;
            dhi = g_qs_hi + base; dlo = g_qs_lo + base;
        } else {
            int kh = (gcol - 1024) >> 6;
            size_t base = ((size_t)(b * NKV_ + kh) * T_ + t) * HD_;
            dhi = g_ks_hi + base; dlo = g_ks_lo + base;
        }
#pragma unroll
        for (int g = 0; g < 4; g++) {
            uint32_t h1[4], l1[4], h2[4], l2[4];
#pragma unroll
            for (int j = 0; j < 4; j++) {
                int d = g * 8 + j * 2;
                float a = o1[d] * sc, bb = o1[d + 1] * sc;
                __nv_bfloat162 hh = __floats2bfloat162_rn(a, bb);
                __nv_bfloat162 ll = __floats2bfloat162_rn(
                    a - __bfloat162float(hh.x), bb - __bfloat162float(hh.y));
                h1[j] = b2u(hh); l1[j] = b2u(ll);
                float a2 = o2[d] * sc, b2f = o2[d + 1] * sc;
                __nv_bfloat162 hh2 = __floats2bfloat162_rn(a2, b2f);
                __nv_bfloat162 ll2 = __floats2bfloat162_rn(
                    a2 - __bfloat162float(hh2.x), b2f - __bfloat162float(hh2.y));
                h2[j] = b2u(hh2); l2[j] = b2u(ll2);
            }
            *(uint4*)(dhi + g * 8)      = make_uint4(h1[0], h1[1], h1[2], h1[3]);
            *(uint4*)(dlo + g * 8)      = make_uint4(l1[0], l1[1], l1[2], l1[3]);
            *(uint4*)(dhi + 32 + g * 8) = make_uint4(h2[0], h2[1], h2[2], h2[3]);
            *(uint4*)(dlo + 32 + g * 8) = make_uint4(l2[0], l2[1], l2[2], l2[3]);
        }
    } else {
        int h = (gcol - 1280) >> 6;
        float gt = gate[row * NKV_ + h];
        const float* vep = ve + (size_t)row * (NKV_ * HD_) + h * HD_;
        size_t base = ((size_t)(b * NKV_ + h) * T_ + t) * HD_;
#pragma unroll
        for (int g = 0; g < 8; g++) {
            uint32_t hq[4], lq[4];
#pragma unroll
            for (int j = 0; j < 4; j++) {
                int d = g * 8 + j * 2;
                float a = v[d] + gt * vep[d];
                float bb = v[d + 1] + gt * vep[d + 1];
                __nv_bfloat162 hh = __floats2bfloat162_rn(a, bb);
                __nv_bfloat162 ll = __floats2bfloat162_rn(
                    a - __bfloat162float(hh.x), bb - __bfloat162float(hh.y));
                hq[j] = b2u(hh); lq[j] = b2u(ll);
            }
            *(uint4*)(g_vn_hi + base + g * 8) = make_uint4(hq[0], hq[1], hq[2], hq[3]);
            *(uint4*)(g_vn_lo + base + g * 8) = make_uint4(lq[0], lq[1], lq[2], lq[3]);
        }
    }
}

// ---------------------------------------------------------------------------
// Tiny prep kernels
// ---------------------------------------------------------------------------
__global__ __launch_bounds__(256) void split_fp32(
    const float* __restrict__ src, __nv_bfloat16* __restrict__ hi,
    __nv_bfloat16* __restrict__ lo, int n) {
    int i = blockIdx.x * 256 + threadIdx.x;
    if (i < n) {
        float v = src[i];
        __nv_bfloat16 h = __float2bfloat16(v);
        hi[i] = h;
        lo[i] = __float2bfloat16(v - __bfloat162float(h));
    }
}

// gate[bt][h] = 2*sigmoid( x[bt,:32] @ Wgate[:,h] ). One warp per token.
__global__ __launch_bounds__(256) void gate_kernel(
    const float* __restrict__ x, const float* __restrict__ Wgate,
    float* __restrict__ gate) {
    int bt = blockIdx.x * 8 + (threadIdx.x >> 5);
    int lane = threadIdx.x & 31;
    float xv = x[(size_t)bt * C_ + lane];
#pragma unroll
    for (int h = 0; h < NKV_; h++) {
        float p = xv * Wgate[lane * NKV_ + h];
#pragma unroll
        for (int o = 16; o; o >>= 1) p += __shfl_xor_sync(0xffffffffu, p, o);
        if (lane == 0) gate[bt * NKV_ + h] = 2.0f / (1.0f + expf(-p));
    }
}

// Combined weight transpose + hi/lo split.
__global__ __launch_bounds__(256) void transpose_split_all(
    const float* __restrict__ Wq, const float* __restrict__ Wk,
    const float* __restrict__ Wv, const float* __restrict__ Wp) {
    __shared__ float t[32][33];
    const int ct = blockIdx.x;
    const float* W;
    __nv_bfloat16 *hi, *lo;
    int Ncols, nb;
    if (ct < 32)      { W = Wq; hi = g_wqkv_hi;                     lo = g_wqkv_lo;                     Ncols = 1024; nb = ct * 32; }
    else if (ct < 40) { W = Wk; hi = g_wqkv_hi + (size_t)1024 * C_; lo = g_wqkv_lo + (size_t)1024 * C_; Ncols = 256;  nb = (ct - 32) * 32; }
    else if (ct < 48) { W = Wv; hi = g_wqkv_hi + (size_t)1280 * C_; lo = g_wqkv_lo + (size_t)1280 * C_; Ncols = 256;  nb = (ct - 40) * 32; }
    else              { W = Wp; hi = g_wproj_hi;                    lo = g_wproj_lo;                    Ncols = 1024; nb = (ct - 48) * 32; }
    const int kb = blockIdx.y * 32;
    const int tx = threadIdx.x, ty = threadIdx.y;
#pragma unroll
    for (int j = 0; j < 32; j += 8)
        t[ty + j][tx] = W[(size_t)(kb + ty + j) * Ncols + nb + tx];
    __syncthreads();
#pragma unroll
    for (int j = 0; j < 32; j += 8) {
        float v = t[tx][ty + j];
        __nv_bfloat16 h = __float2bfloat16(v);
        size_t o = (size_t)(nb + ty + j) * C_ + kb + tx;
        hi[o] = h;
        lo[o] = __float2bfloat16(v - __bfloat162float(h));
    }
}

// V layout transpose: [T, HD] -> [HD, T] per (b, kvh), hi+lo, via smem tiles.
__global__ __launch_bounds__(256) void transpose_v() {
    __shared__ __nv_bfloat16 th[32][34], tl[32][34];
    const int tb = blockIdx.x * 32;
    const int db = blockIdx.y * 32;
    const int m  = blockIdx.z;
    const int tx = threadIdx.x, ty = threadIdx.y;
    const __nv_bfloat16* sh = g_vn_hi + (size_t)m * T_ * HD_;
    const __nv_bfloat16* sl = g_vn_lo + (size_t)m * T_ * HD_;
#pragma unroll
    for (int j = 0; j < 32; j += 8) {
        th[ty + j][tx] = sh[(size_t)(tb + ty + j) * HD_ + db + tx];
        tl[ty + j][tx] = sl[(size_t)(tb + ty + j) * HD_ + db + tx];
    }
    __syncthreads();
    __nv_bfloat16* dh = g_vts_hi + (size_t)m * HD_ * T_;
    __nv_bfloat16* dl = g_vts_lo + (size_t)m * HD_ * T_;
#pragma unroll
    for (int j = 0; j < 32; j += 8) {
        dh[(size_t)(db + ty + j) * T_ + tb + tx] = th[tx][ty + j];
        dl[(size_t)(db + ty + j) * T_ + tb + tx] = tl[tx][ty + j];
    }
}

// ---------------------------------------------------------------------------
// Split-bf16 GEMM: C = (Ahi+Alo).(Bhi+Blo)^T, 3-term, all operands pre-split.
// 3-STAGE cp.async pipeline, MMA queue depth 2 (wait MMA(i-2)).
// mode 0: write fp32 C. mode 1: fused QKV epilogue (RoPE/RMSNorm/gate-V).
// grid = (N/128, M/128), 256 threads.
// ---------------------------------------------------------------------------
#define KCHUNK   64
#define NCHUNKS  (C_ / KCHUNK)           // 16
#define BUFSZ    16384                   // 128 rows x 128 bytes
#define STAGESZ  (4 * BUFSZ)             // Ahi | Alo | Bhi | Blo
#define GEMM_SMEM (2048 + 3 * STAGESZ)   // 198656

__global__ __launch_bounds__(256) void gemm_split(
    const __nv_bfloat16* __restrict__ Ahi, const __nv_bfloat16* __restrict__ Alo,
    const __nv_bfloat16* __restrict__ Bhi, const __nv_bfloat16* __restrict__ Blo,
    float* __restrict__ C, int N, int mode,
    const float* __restrict__ cosb, const float* __restrict__ sinb,
    const float* __restrict__ ve, const float* __restrict__ gate) {
    extern __shared__ char smem[];
#if TC_OK
    const uint32_t sb = smem_u32(smem);
    const uint32_t ab = (sb + 1024 + 1023) & 0xFFFFFC00u;
    const int tid = threadIdx.x;
    const int wid = tid >> 5;
    const int lane = tid & 31;
    const int bm = blockIdx.y * 128;
    const int bn = blockIdx.x * 128;
    const int K = C_;

    if (wid == 0) TC_ALLOC(sb, 128);
    if (tid == 0) { MBAR_INIT(sb + 8, 1); MBAR_INIT(sb + 16, 1); MBAR_INIT(sb + 24, 1); }
    __syncthreads();
    uint32_t tmem;
    asm volatile("ld.shared.b32 %0, [%1];" : "=r"(tmem) : "r"(sb));

#define LOAD_CHUNK(kc, s)                                                     \
    do {                                                                      \
        const int k0 = (kc) * KCHUNK;                                         \
        uint32_t st = ab + (s) * STAGESZ;                                     \
        _Pragma("unroll")                                                     \
        for (int v = 0; v < 4; v++) {                                         \
            int idx = tid + v * 256;                                          \
            int r = idx >> 3, c8 = idx & 7;                                   \
            uint32_t off = SW128((uint32_t)(r * 128 + c8 * 16));              \
            size_t ga = (size_t)(bm + r) * K + k0 + c8 * 8;                   \
            size_t gb = (size_t)(bn + r) * K + k0 + c8 * 8;                   \
            CP_ASYNC16(st + off,              Ahi + ga);                      \
            CP_ASYNC16(st + BUFSZ + off,      Alo + ga);                      \
            CP_ASYNC16(st + 2 * BUFSZ + off,  Bhi + gb);                      \
            CP_ASYNC16(st + 3 * BUFSZ + off,  Blo + gb);                      \
        }                                                                     \
        CP_COMMIT();                                                          \
    } while (0)

    LOAD_CHUNK(0, 0);
    int pc0 = 0, pc1 = 0, pc2 = 0;

    for (int i = 0; i < NCHUNKS; i++) {
        const int s = i % 3;
        // free the stage chunk i+1 will use: its last reader was MMA(i-2)
        if (i >= 2) {
            const int ws = (i + 1) % 3;
            if (ws == 0)      { mbar_wait(sb + 8,  pc0 & 1); pc0++; }
            else if (ws == 1) { mbar_wait(sb + 16, pc1 & 1); pc1++; }
            else              { mbar_wait(sb + 24, pc2 & 1); pc2++; }
        }
        if (i + 1 < NCHUNKS) LOAD_CHUNK(i + 1, (i + 1) % 3);
        else CP_COMMIT();            // empty group keeps wait counts uniform
        CP_WAIT1();                  // chunk i resident (chunk i+1 pending)
        __syncthreads();
        if (wid == 0) {
            FENCE_ASYNC();
            if (elect_one()) {
                uint32_t base = ab + s * STAGESZ;
                uint64_t dah = smem_desc_sw128(base);
                uint64_t dal = smem_desc_sw128(base + BUFSZ);
                uint64_t dbh = smem_desc_sw128(base + 2 * BUFSZ);
                uint64_t dbl = smem_desc_sw128(base + 3 * BUFSZ);
#pragma unroll
                for (int kk = 0; kk < 4; kk++)
                    mma_f16_ss(tmem, dah + kk * 2, dbh + kk * 2, GEMM_IDESC,
                               (i > 0) || (kk > 0));
#pragma unroll
                for (int kk = 0; kk < 4; kk++)
                    mma_f16_ss(tmem, dah + kk * 2, dbl + kk * 2, GEMM_IDESC, 1);
#pragma unroll
                for (int kk = 0; kk < 4; kk++)
                    mma_f16_ss(tmem, dal + kk * 2, dbh + kk * 2, GEMM_IDESC, 1);
                TC_COMMIT(sb + 8 + s * 8);
            }
        }
    }
    {
        const int sl = (NCHUNKS - 1) % 3;
        if (sl == 0)      mbar_wait(sb + 8,  pc0 & 1);
        else if (sl == 1) mbar_wait(sb + 16, pc1 & 1);
        else              mbar_wait(sb + 24, pc2 & 1);
    }
    TC_FENCE_AFTER();

    {
        const int sp = wid & 3;
        const int colbase = (wid >> 2) * 64;
        const uint32_t wo = (uint32_t)sp << 21;
        uint32_t d0[32], d1[32];
        LDTM_X32(d0, tmem + wo + colbase);
        LDTM_X32(d1, tmem + wo + colbase + 32);
        TC_WAIT_LD();
        const int row = bm + sp * 32 + lane;
        if (mode == 0) {
            float* dst = C + (size_t)row * N + bn + colbase;
#pragma unroll
            for (int c = 0; c < 32; c += 4) {
                *(float4*)(dst + c) = make_float4(
                    __uint_as_float(d0[c]), __uint_as_float(d0[c + 1]),
                    __uint_as_float(d0[c + 2]), __uint_as_float(d0[c + 3]));
                *(float4*)(dst + 32 + c) = make_float4(
                    __uint_as_float(d1[c]), __uint_as_float(d1[c + 1]),
                    __uint_as_float(d1[c + 2]), __uint_as_float(d1[c + 3]));
            }
        } else {
            float vv[64];
#pragma unroll
            for (int c = 0; c < 32; c++) {
                vv[c] = __uint_as_float(d0[c]);
                vv[32 + c] = __uint_as_float(d1[c]);
            }
            fused_rowhead(vv, row, bn + colbase, cosb, sinb, ve, gate);
        }
    }
    __syncthreads();
    if (wid == 0) TC_DEALLOC(tmem, 128);
#undef LOAD_CHUNK

#else  // -------------------------- SIMT fallback --------------------------
    __shared__ float As[8][128];
    __shared__ float Bs[8][128];
    const int tid = threadIdx.x;
    const int bm = blockIdx.y * 128;
    const int bn = blockIdx.x * 128;
    const int K = C_;
    const int ldRow = tid >> 1;
    const int ldK   = (tid & 1) * 4;
    const int ri = (tid >> 4) * 4;
    const int ci = (tid & 15) * 4;

    float acc[8][8];
#pragma unroll
    for (int i = 0; i < 8; i++)
#pragma unroll
        for (int j = 0; j < 8; j++) acc[i][j] = 0.f;

    for (int k0 = 0; k0 < K; k0 += 8) {
#pragma unroll
        for (int c = 0; c < 4; c++) {
            size_t ga = (size_t)(bm + ldRow) * K + k0 + ldK + c;
            size_t gb = (size_t)(bn + ldRow) * K + k0 + ldK + c;
            As[ldK + c][ldRow] = __bfloat162float(Ahi[ga]) + __bfloat162float(Alo[ga]);
            Bs[ldK + c][ldRow] = __bfloat162float(Bhi[gb]) + __bfloat162float(Blo[gb]);
        }
        __syncthreads();
#pragma unroll
        for (int kk = 0; kk < 8; kk++) {
            float ar[8], br[8];
#pragma unroll
            for (int i = 0; i < 4; i++) {
                ar[i] = As[kk][ri + i];
                ar[i + 4] = As[kk][ri + 64 + i];
                br[i] = Bs[kk][ci + i];
                br[i + 4] = Bs[kk][ci + 64 + i];
            }
#pragma unroll
            for (int i = 0; i < 8; i++)
#pragma unroll
                for (int j = 0; j < 8; j++) acc[i][j] += ar[i] * br[j];
        }
        __syncthreads();
    }
    if (mode == 0) {
#pragma unroll
        for (int ib = 0; ib < 2; ib++)
#pragma unroll
            for (int i = 0; i < 4; i++) {
                int row = bm + ib * 64 + ri + i;
#pragma unroll
                for (int jb = 0; jb < 2; jb++)
#pragma unroll
                    for (int j = 0; j < 4; j++)
                        C[(size_t)row * N + bn + jb * 64 + ci + j] =
                            acc[ib * 4 + i][jb * 4 + j];
            }
    } else {
        // stage the 128x128 tile in dynamic smem, then per-(row,head) fuse
        float* tile = (float*)smem;
#pragma unroll
        for (int ib = 0; ib < 2; ib++)
#pragma unroll
            for (int i = 0; i < 4; i++)
#pragma unroll
                for (int jb = 0; jb < 2; jb++)
#pragma unroll
                    for (int j = 0; j < 4; j++)
                        tile[(ib * 64 + ri + i) * 128 + jb * 64 + ci + j] =
                            acc[ib * 4 + i][jb * 4 + j];
        __syncthreads();
        int r2 = tid >> 1, hh = (tid & 1) * 64;
        float vv[64];
#pragma unroll
        for (int d = 0; d < 64; d++) vv[d] = tile[r2 * 128 + hh + d];
        fused_rowhead(vv, bm + r2, bn + hh, cosb, sinb, ve, gate);
    }
#endif
}

// ---------------------------------------------------------------------------
// tcgen05 sliding-window flash attention (unchanged from round 15).
// ---------------------------------------------------------------------------
#define AOFF_RED 0         // redsum[256] f32 (1KB)
#define AOFF_Q   2048      // Qhi 16K | Qlo 16K                 (end 34816)
#define AOFF_K   34816     // buf s: {Khi 8K | Klo 8K} x2       (end 67584)
#define AOFF_V   67584     // buf s: {Vhi 8K | Vlo 8K} x2       (end 100352)
#define KBUF(s)  (AOFF_K + (s) * 16384)
#define VBUF(s)  (AOFF_V + (s) * 16384)
#define ATT_SMEM 103424

#define TM_S(s)  ((s) * 64)
#define TM_PV    128
#define TM_PHI   192
#define TM_PLO   224

__global__ __launch_bounds__(256, 2) void attn_tc(const int* __restrict__ winp) {
#if TC_OK
    extern __shared__ char smem[];
    const uint32_t sb = smem_u32(smem);
    const uint32_t ab = (sb + 1024 + 1023) & 0xFFFFFC00u;
    char* abp = smem + (ab - sb);

    int win = winp[0];
    if (win <= 0 || win > T_) win = 1024;
    const int qt = blockIdx.x, h = blockIdx.y, b = blockIdx.z;
    const int kvh = h >> 2;
    const int q0 = qt * 128;
    const int tid = threadIdx.x, w = tid >> 5, lane = tid & 31;
    const int sp = w & 3;
    const int hf = w >> 2;
    const int kbase = hf * 32;
    const int r = sp * 32 + lane;
    const int qg = q0 + r;
    const uint32_t wo = (uint32_t)sp << 21;

    float* redsum = (float*)(abp + AOFF_RED);

    if (w == 0) { TC_ALLOC(sb, 256); TC_RELINQ(); }
    if (tid == 0) { MBAR_INIT(sb + 8, 1); MBAR_INIT(sb + 16, 1); }
    __syncthreads();
    uint32_t tmem;
    asm volatile("ld.shared.b32 %0, [%1];" : "=r"(tmem) : "r"(sb));

    const __nv_bfloat16* qh  = g_qs_hi  + ((size_t)(b * NH_ + h) * T_ + q0) * HD_;
    const __nv_bfloat16* qlo = g_qs_lo  + ((size_t)(b * NH_ + h) * T_ + q0) * HD_;
    const __nv_bfloat16* kh  = g_ks_hi  + ((size_t)(b * NKV_ + kvh) * T_) * HD_;
    const __nv_bfloat16* kl  = g_ks_lo  + ((size_t)(b * NKV_ + kvh) * T_) * HD_;
    const __nv_bfloat16* vth = g_vts_hi + ((size_t)(b * NKV_ + kvh) * HD_) * T_;
    const __nv_bfloat16* vtl = g_vts_lo + ((size_t)(b * NKV_ + kvh) * HD_) * T_;

    int j0s = q0 - win;
    if (j0s < 0) j0s = 0;
    const int jt0 = j0s >> 6;
    const int jt1 = (q0 + 127) >> 6;

    const int krr0 = tid >> 3, kc8 = (tid & 7) * 8;
    const uint32_t koff0 = SW128((uint32_t)(krr0 * 128 + kc8 * 2));
    const uint32_t koff1 = SW128((uint32_t)((krr0 + 32) * 128 + kc8 * 2));

#define LOAD_K(jt, s)                                                         \
    do {                                                                      \
        const int j0_ = (jt) * 64;                                            \
        uint32_t kb_ = ab + KBUF(s);                                          \
        CP_ASYNC16(kb_ + koff0,        kh + (size_t)(j0_ + krr0) * 64 + kc8); \
        CP_ASYNC16(kb_ + koff1,        kh + (size_t)(j0_ + krr0 + 32) * 64 + kc8); \
        CP_ASYNC16(kb_ + 8192 + koff0, kl + (size_t)(j0_ + krr0) * 64 + kc8); \
        CP_ASYNC16(kb_ + 8192 + koff1, kl + (size_t)(j0_ + krr0 + 32) * 64 + kc8); \
    } while (0)

#define LOAD_V(jt, s)                                                         \
    do {                                                                      \
        const int j0_ = (jt) * 64;                                            \
        uint32_t vb_ = ab + VBUF(s);                                          \
        CP_ASYNC16(vb_ + koff0,        vth + (size_t)krr0 * T_ + j0_ + kc8);  \
        CP_ASYNC16(vb_ + koff1,        vth + (size_t)(krr0 + 32) * T_ + j0_ + kc8); \
        CP_ASYNC16(vb_ + 8192 + koff0, vtl + (size_t)krr0 * T_ + j0_ + kc8);  \
        CP_ASYNC16(vb_ + 8192 + koff1, vtl + (size_t)(krr0 + 32) * T_ + j0_ + kc8); \
    } while (0)

#define ISSUE_S(kbuf_s, tm_s)                                                 \
    do {                                                                      \
        uint64_t dKh = smem_desc_sw128(ab + KBUF(kbuf_s));                    \
        uint64_t dKl = smem_desc_sw128(ab + KBUF(kbuf_s) + 8192);             \
        uint32_t sdst = tmem + TM_S(tm_s);                                    \
        _Pragma("unroll")                                                     \
        for (int kk = 0; kk < 4; kk++)                                        \
            mma_f16_ss(sdst, dQh + kk * 2, dKh + kk * 2, ATT_IDESC, kk > 0);  \
        _Pragma("unroll")                                                     \
        for (int kk = 0; kk < 4; kk++)                                        \
            mma_f16_ss(sdst, dQh + kk * 2, dKl + kk * 2, ATT_IDESC, 1);       \
        _Pragma("unroll")                                                     \
        for (int kk = 0; kk < 4; kk++)                                        \
            mma_f16_ss(sdst, dQl + kk * 2, dKh + kk * 2, ATT_IDESC, 1);       \
    } while (0)

    // ---- prologue ----
#pragma unroll
    for (int v = 0; v < 4; v++) {
        int idx = tid + v * 256;
        int rr = idx >> 3, c8 = idx & 7;
        uint32_t off = SW128((uint32_t)(rr * 128 + c8 * 16));
        *(uint4*)(abp + AOFF_Q + off)         = *(const uint4*)(qh  + rr * 64 + c8 * 8);
        *(uint4*)(abp + AOFF_Q + 16384 + off) = *(const uint4*)(qlo + rr * 64 + c8 * 8);
    }
    LOAD_K(jt0, jt0 & 1);
    LOAD_V(jt0, jt0 & 1);
    CP_COMMIT();
    LOAD_K(jt0 + 1, (jt0 + 1) & 1);
    CP_COMMIT();
    CP_WAIT0();
    __syncthreads();
    const uint64_t dQh = smem_desc_sw128(ab + AOFF_Q);
    const uint64_t dQl = smem_desc_sw128(ab + AOFF_Q + 16384);
    if (w == 0) {
        FENCE_ASYNC();
        if (elect_one()) {
            ISSUE_S(jt0 & 1, jt0 & 1);
            TC_COMMIT(sb + 8);
        }
    }

    float l_loc = 0.f;
    int ps = 0, ppv = 0;
    const float C1 = 0.18033688f;      // 0.125 * log2(e)
    const float C0 = -11.541560f;      // -8 * log2(e)

    for (int jt = jt0; jt <= jt1; jt++) {
        const int sbuf = jt & 1;
        const int j0 = jt * 64;
        mbar_wait(sb + 8, ps & 1); ps++;
        CP_WAIT1();
        __syncthreads();
        TC_FENCE_AFTER();
        if (jt < jt1 && w == 0) {
            FENCE_ASYNC();
            if (elect_one()) {
                ISSUE_S(sbuf ^ 1, sbuf ^ 1);
                TC_COMMIT(sb + 8);
            }
        }
        {
            int kidx = jt + 2 <= jt1 ? jt + 2 : jt1;
            LOAD_K(kidx, sbuf);
            CP_COMMIT();
        }
        uint32_t sr[32];
        LDTM_X32(sr, tmem + wo + TM_S(sbuf) + kbase);
        TC_WAIT_LD();
        float p[32];
#pragma unroll
        for (int i = 0; i < 32; i++) {
            int jg = j0 + kbase + i;
            bool ok = (jg <= qg) && (jg >= qg - win);
            float e = ex2_approx(fmaf(__uint_as_float(sr[i]), C1, C0));
            p[i] = ok ? e : 0.f;
            l_loc += p[i];
        }
        if (jt > jt0) { mbar_wait(sb + 16, ppv & 1); ppv++; TC_FENCE_AFTER(); }
        {
            uint32_t ph[16], pl[16];
#pragma unroll
            for (int i = 0; i < 16; i++) {
                float pa = p[2 * i], pb = p[2 * i + 1];
                __nv_bfloat162 hh = __floats2bfloat162_rn(pa, pb);
                float la = pa - __bfloat162float(hh.x);
                float lb = pb - __bfloat162float(hh.y);
                __nv_bfloat162 ll = __floats2bfloat162_rn(la, lb);
                ph[i] = b2u(hh);
                pl[i] = b2u(ll);
            }
            STTM_X16(tmem + wo + TM_PHI + hf * 16, ph);
            STTM_X16(tmem + wo + TM_PLO + hf * 16, pl);
            TC_WAIT_ST();
            TC_FENCE_BEFORE();
        }
        CP_WAIT1();
        {
            int vidx = jt + 1 <= jt1 ? jt + 1 : jt1;
            LOAD_V(vidx, sbuf ^ 1);
            CP_COMMIT();
        }
        __syncthreads();
        if (w == 0) {
            TC_FENCE_AFTER();
            FENCE_ASYNC();
            if (elect_one()) {
                uint64_t dVh = smem_desc_sw128(ab + VBUF(sbuf));
                uint64_t dVl = smem_desc_sw128(ab + VBUF(sbuf) + 8192);
#pragma unroll
                for (int kk = 0; kk < 4; kk++)
                    mma_f16_ts(tmem + TM_PV, tmem + TM_PHI + kk * 8,
                               dVh + kk * 2, ATT_IDESC, (jt > jt0) || (kk > 0));
#pragma unroll
                for (int kk = 0; kk < 4; kk++)
                    mma_f16_ts(tmem + TM_PV, tmem + TM_PHI + kk * 8,
                               dVl + kk * 2, ATT_IDESC, 1);
#pragma unroll
                for (int kk = 0; kk < 4; kk++)
                    mma_f16_ts(tmem + TM_PV, tmem + TM_PLO + kk * 8,
                               dVh + kk * 2, ATT_IDESC, 1);
                TC_COMMIT(sb + 16);
            }
        }
    }
    // drain final PV, combine l halves, write ys hi/lo (bf16 split)
    mbar_wait(sb + 16, ppv & 1);
    TC_FENCE_AFTER();
    redsum[r * 2 + hf] = l_loc;
    __syncthreads();
    const float l = redsum[r * 2] + redsum[r * 2 + 1];
    uint32_t pr[32];
    LDTM_X32(pr, tmem + wo + TM_PV + kbase);
    TC_WAIT_LD();
    {
        const float inv = 1.0f / l;
        size_t orow = ((size_t)(b * T_ + qg)) * C_ + h * 64 + kbase;
#pragma unroll
        for (int i = 0; i < 16; i++) {
            float va = __uint_as_float(pr[2 * i]) * inv;
            float vb = __uint_as_float(pr[2 * i + 1]) * inv;
            __nv_bfloat162 hh = __floats2bfloat162_rn(va, vb);
            float la = va - __bfloat162float(hh.x);
            float lb = vb - __bfloat162float(hh.y);
            __nv_bfloat162 ll = __floats2bfloat162_rn(la, lb);
            *(uint32_t*)(g_ys_hi + orow + 2 * i) = b2u(hh);
            *(uint32_t*)(g_ys_lo + orow + 2 * i) = b2u(ll);
        }
    }
    __syncthreads();
    if (w == 0) TC_DEALLOC(tmem, 256);
#undef LOAD_K
#undef LOAD_V
#undef ISSUE_S

#else  // ---------------- SIMT fallback (baseline target, never run) --------
    const int qt = blockIdx.x, h = blockIdx.y, b = blockIdx.z;
    const int kvh = h >> 2;
    int win = winp[0];
    if (win <= 0 || win > T_) win = 1024;
    const int tid = threadIdx.x;
    if (tid < 128) {
        const int qg = qt * 128 + tid;
        const __nv_bfloat16* qh  = g_qs_hi + ((size_t)(b * NH_ + h) * T_ + qg) * HD_;
        const __nv_bfloat16* qlo = g_qs_lo + ((size_t)(b * NH_ + h) * T_ + qg) * HD_;
        float q[64];
        for (int d = 0; d < 64; d++)
            q[d] = __bfloat162float(qh[d]) + __bfloat162float(qlo[d]);
        const __nv_bfloat16* kh  = g_ks_hi  + ((size_t)(b * NKV_ + kvh) * T_) * HD_;
        const __nv_bfloat16* kl  = g_ks_lo  + ((size_t)(b * NKV_ + kvh) * T_) * HD_;
        const __nv_bfloat16* vth = g_vts_hi + ((size_t)(b * NKV_ + kvh) * HD_) * T_;
        const __nv_bfloat16* vtl = g_vts_lo + ((size_t)(b * NKV_ + kvh) * HD_) * T_;
        float l = 0.f, O[64];
        for (int d = 0; d < 64; d++) O[d] = 0.f;
        int js = qg - win;
        if (js < 0) js = 0;
        for (int j = js; j <= qg; j++) {
            float s = 0.f;
            for (int d = 0; d < 64; d++)
                s += q[d] * (__bfloat162float(kh[(size_t)j * 64 + d]) +
                             __bfloat162float(kl[(size_t)j * 64 + d]));
            float p = __expf(s * 0.125f - 8.0f);
            l += p;
            for (int d = 0; d < 64; d++)
                O[d] += p * (__bfloat162float(vth[(size_t)d * T_ + j]) +
                             __bfloat162float(vtl[(size_t)d * T_ + j]));
        }
        float inv = 1.0f / l;
        size_t orow = ((size_t)(b * T_ + qg)) * C_ + h * 64;
        for (int d = 0; d < 64; d++) {
            float vO = O[d] * inv;
            __nv_bfloat16 hh = __float2bfloat16(vO);
            g_ys_hi[orow + d] = hh;
            g_ys_lo[orow + d] = __float2bfloat16(vO - __bfloat162float(hh));
        }
    }
#endif
}

// ---------------------------------------------------------------------------
// Launch
// ---------------------------------------------------------------------------
extern "C" void kernel_launch(void* const* d_in, const int* in_sizes, int n_in,
                              void* d_out, int out_size) {
    const float* x     = (const float*)d_in[0];
    const float* ve    = (const float*)d_in[1];
    const float* cosb  = (const float*)d_in[2];
    const float* sinb  = (const float*)d_in[3];
    const float* Wq    = (const float*)d_in[4];
    const float* Wk    = (const float*)d_in[5];
    const float* Wv    = (const float*)d_in[6];
    const float* Wproj = (const float*)d_in[7];
    const float* Wgate = (const float*)d_in[8];
    const int*   win   = (const int*)d_in[9];
    float* out = (float*)d_out;

    __nv_bfloat16 *xs_hi, *xs_lo, *ys_hi, *ys_lo,
                  *wqkv_hi, *wqkv_lo, *wproj_hi, *wproj_lo;
    float *gatep;
    cudaGetSymbolAddress((void**)&xs_hi, g_xs_hi);
    cudaGetSymbolAddress((void**)&xs_lo, g_xs_lo);
    cudaGetSymbolAddress((void**)&ys_hi, g_ys_hi);
    cudaGetSymbolAddress((void**)&ys_lo, g_ys_lo);
    cudaGetSymbolAddress((void**)&wqkv_hi, g_wqkv_hi);
    cudaGetSymbolAddress((void**)&wqkv_lo, g_wqkv_lo);
    cudaGetSymbolAddress((void**)&wproj_hi, g_wproj_hi);
    cudaGetSymbolAddress((void**)&wproj_lo, g_wproj_lo);
    cudaGetSymbolAddress((void**)&gatep, g_gate);

    cudaFuncSetAttribute(gemm_split,
                         cudaFuncAttributeMaxDynamicSharedMemorySize, GEMM_SMEM);
    cudaFuncSetAttribute(attn_tc,
                         cudaFuncAttributeMaxDynamicSharedMemorySize, ATT_SMEM);

    // 1. weight prep + x split + gate
    transpose_split_all<<<dim3(80, C_ / 32), dim3(32, 8)>>>(Wq, Wk, Wv, Wproj);
    split_fp32<<<(M_ * C_ + 255) / 256, 256>>>(x, xs_hi, xs_lo, M_ * C_);
    gate_kernel<<<M_ / 8, 256>>>(x, Wgate, gatep);
    // 2. fused QKV projection + RoPE/RMSNorm/gate-V epilogue (mode 1)
    gemm_split<<<dim3(NQKV_ / 128, M_ / 128), 256, GEMM_SMEM>>>(
        xs_hi, xs_lo, wqkv_hi, wqkv_lo, nullptr, NQKV_, 1,
        cosb, sinb, ve, gatep);
    // 3. V layout transpose
    transpose_v<<<dim3(T_ / 32, HD_ / 32, B_ * NKV_), dim3(32, 8)>>>();
    // 4. deep-pipelined tensor-core attention (writes ys hi/lo directly)
    attn_tc<<<dim3(T_ / 128, NH_, B_), 256, ATT_SMEM>>>(win);
    // 5. output projection (mode 0: plain fp32 C)
    gemm_split<<<dim3(C_ / 128, M_ / 128), 256, GEMM_SMEM>>>(
        ys_hi, ys_lo, wproj_hi, wproj_lo, out, C_, 0,
        nullptr, nullptr, nullptr, nullptr);
}